// round 6
// baseline (speedup 1.0000x reference)
#include <cuda_runtime.h>

#define BB 512
#define DD 1024
#define HH 512
#define CC 4
#define DCH 8
#define KK (DD / DCH)       // 128 chunks
#define NSEG 4
#define HITER (HH / NSEG)   // 128 per hseg

// P'[k][h][b] = 0.5*(c + sum_{j<8k} x[b,j]W[h,j]); +BB pad for prefetch overrun
__device__ float g_P[((size_t)KK * HH + 1) * BB];      // ~134 MB, streamed
// xT[d][b] = 0.5 * x[b][d]
__device__ float g_XT[(size_t)DD * BB];
// vb[d][c] = bias[d][c] + 0.5 * sum_h V[h][d][c]
__device__ float g_VB[DD * CC];

__device__ __forceinline__ float tanh_fast(float a) {
    float th;
    asm("tanh.approx.f32 %0, %1;" : "=f"(th) : "f"(a));
    return th;
}

// ---------------- Phase 0a: vb = bias + 0.5 * sum_h V ----------------
// 32 blocks x 512 thr: 128 i's per block, h split 4 ways, smem reduce.
__global__ __launch_bounds__(512) void nade_vb(
    const float* __restrict__ V, const float* __restrict__ bias)
{
    __shared__ float part[4][128];
    const int il = threadIdx.x & 127;
    const int seg = threadIdx.x >> 7;            // 0..3
    const int i = blockIdx.x * 128 + il;
    float s = 0.f;
    const float* Vp = V + (size_t)(seg * 128) * (DD * CC) + i;
#pragma unroll 8
    for (int h = 0; h < 128; h++)
        s += __ldg(Vp + (size_t)h * (DD * CC));
    part[seg][il] = s;
    __syncthreads();
    if (seg == 0) {
        float t = part[0][il] + part[1][il] + part[2][il] + part[3][il];
        g_VB[i] = fmaf(0.5f, t, __ldg(&bias[i]));
    }
}

// ---------------- Phase 0b: xT[d][b] = 0.5 * x[b][d] ----------------
__global__ __launch_bounds__(256) void nade_xt(const float* __restrict__ x)
{
    __shared__ float tile[32][33];
    const int b0 = blockIdx.x * 32;
    const int d0 = blockIdx.y * 32;
    const int tx = threadIdx.x;       // 0..31
    const int ty = threadIdx.y;       // 0..7
#pragma unroll
    for (int r = 0; r < 4; r++)
        tile[ty + 8 * r][tx] = __ldg(&x[(size_t)(b0 + ty + 8 * r) * DD + d0 + tx]);
    __syncthreads();
#pragma unroll
    for (int r = 0; r < 4; r++)
        g_XT[(size_t)(d0 + ty + 8 * r) * BB + b0 + tx] = 0.5f * tile[tx][ty + 8 * r];
}

// ---------------- Phase 1: prefix GEMM, snapshots every 8 j ----------------
// grid (HH/16, BB/32), block 128: bl = tid&31 (b), hg = tid>>5 -> 4 h each.
__global__ __launch_bounds__(128) void nade_phase1(
    const float* __restrict__ W, const float* __restrict__ cvec)
{
    const int tid = threadIdx.x;
    const int bl = tid & 31;
    const int hg = tid >> 5;                       // 0..3
    const int hbase = blockIdx.x * 16 + hg * 4;    // 4 consecutive h
    const int b = blockIdx.y * 32 + bl;

    float acc[4];
#pragma unroll
    for (int m = 0; m < 4; m++) acc[m] = 0.5f * __ldg(&cvec[hbase + m]);

#pragma unroll 2
    for (int k = 0; k < KK; k++) {
        float* Pk = g_P + ((size_t)k * HH + hbase) * BB + b;
#pragma unroll
        for (int m = 0; m < 4; m++) Pk[(size_t)m * BB] = acc[m];

        float xv[DCH];
#pragma unroll
        for (int j = 0; j < DCH; j++)
            xv[j] = g_XT[(size_t)(k * DCH + j) * BB + b];          // coalesced L2

#pragma unroll
        for (int m = 0; m < 4; m++) {
            const float4* wr = (const float4*)(W + (size_t)(hbase + m) * DD + k * DCH);
#pragma unroll
            for (int q = 0; q < 2; q++) {
                float4 w = __ldg(&wr[q]);                           // warp-uniform
                acc[m] = fmaf(xv[4 * q + 0], w.x, acc[m]);
                acc[m] = fmaf(xv[4 * q + 1], w.y, acc[m]);
                acc[m] = fmaf(xv[4 * q + 2], w.z, acc[m]);
                acc[m] = fmaf(xv[4 * q + 3], w.w, acc[m]);
            }
        }
    }
}

// ---------------- Phase 2: per-chunk sequential NADE, 2 b per lane ----------------
// grid (KK, BB/64), block 128 = 4 warps (one per hseg). Lane: b0+lane, b0+lane+32.
__global__ __launch_bounds__(128, 4) void nade_phase2(
    const float* __restrict__ V, const float* __restrict__ W,
    float* __restrict__ out)
{
    __shared__ float ws[HH][DCH];                 // 16 KB: W[h][d0:d0+8]
    __shared__ float red[NSEG - 1][DCH * CC][64]; // 24 KB

    const int k = blockIdx.x;
    const int b0 = blockIdx.y * 64;
    const int tid = threadIdx.x;
    const int lane = tid & 31;
    const int hseg = tid >> 5;                    // 0..3
    const int ba = b0 + lane;
    const int bb = ba + 32;
    const int d0 = k * DCH;

    // stage W slice: 512 rows x 32B
    for (int i = tid; i < HH * 2; i += 128) {
        const int hh = i >> 1, q = i & 1;
        float4 wv = __ldg((const float4*)(W + (size_t)hh * DD + d0) + q);
        *(float4*)&ws[hh][q * 4] = wv;
    }

    // preload 0.5*x for both b (coalesced from xT)
    float xa[DCH], xb[DCH];
#pragma unroll
    for (int j = 0; j < DCH; j++) {
        const float* xr = &g_XT[(size_t)(d0 + j) * BB + b0];
        xa[j] = xr[lane];
        xb[j] = xr[lane + 32];
    }

    float acca[DCH][CC], accb[DCH][CC];
#pragma unroll
    for (int d = 0; d < DCH; d++)
#pragma unroll
        for (int c = 0; c < CC; c++) { acca[d][c] = 0.f; accb[d][c] = 0.f; }

    __syncthreads();

    const int hstart = hseg * HITER;
    const float* Pp = g_P + ((size_t)k * HH + hstart) * BB + ba;
    const float4* Vp = (const float4*)V + ((size_t)hstart * DD + d0);

    float a0n = __ldg(Pp);
    float a1n = __ldg(Pp + 32);
    for (int it = 0; it < HITER; ++it) {
        float a0 = a0n, a1 = a1n;
        Pp += BB;
        a0n = __ldg(Pp);                         // pad row protects last read
        a1n = __ldg(Pp + 32);
        const float* wr = ws[hstart + it];
#pragma unroll
        for (int q = 0; q < 2; q++) {
            float4 w4 = *(const float4*)(wr + 4 * q);   // broadcast LDS.128
            float wq[4] = {w4.x, w4.y, w4.z, w4.w};
#pragma unroll
            for (int r = 0; r < 4; r++) {
                const int d = 4 * q + r;
                float4 v = __ldg(Vp + d);               // warp-uniform, shared by both b
                float t0 = tanh_fast(a0);
                float t1 = tanh_fast(a1);
                acca[d][0] = fmaf(t0, v.x, acca[d][0]);
                acca[d][1] = fmaf(t0, v.y, acca[d][1]);
                acca[d][2] = fmaf(t0, v.z, acca[d][2]);
                acca[d][3] = fmaf(t0, v.w, acca[d][3]);
                accb[d][0] = fmaf(t1, v.x, accb[d][0]);
                accb[d][1] = fmaf(t1, v.y, accb[d][1]);
                accb[d][2] = fmaf(t1, v.z, accb[d][2]);
                accb[d][3] = fmaf(t1, v.w, accb[d][3]);
                a0 = fmaf(xa[d], wq[r], a0);            // halved-prefix advance
                a1 = fmaf(xb[d], wq[r], a1);
            }
        }
        Vp += DD;
    }

    if (hseg > 0) {
#pragma unroll
        for (int d = 0; d < DCH; d++)
#pragma unroll
            for (int c = 0; c < CC; c++) {
                red[hseg - 1][d * CC + c][lane] = acca[d][c];
                red[hseg - 1][d * CC + c][lane + 32] = accb[d][c];
            }
    }
    __syncthreads();

    if (hseg == 0) {
        float* ya = out + (size_t)ba * (DD * CC) + (size_t)d0 * CC;
        float* yb = out + (size_t)bb * (DD * CC) + (size_t)d0 * CC;
        const size_t pofs = (size_t)BB * DD * CC;
#pragma unroll
        for (int d = 0; d < DCH; d++) {
            const float4 vb = *(const float4*)&g_VB[(d0 + d) * CC];
            float la[4], lb[4];
#pragma unroll
            for (int c = 0; c < CC; c++) {
                float sa = acca[d][c] + red[0][d * CC + c][lane]
                         + red[1][d * CC + c][lane] + red[2][d * CC + c][lane];
                float sb = accb[d][c] + red[0][d * CC + c][lane + 32]
                         + red[1][d * CC + c][lane + 32] + red[2][d * CC + c][lane + 32];
                la[c] = fmaf(0.5f, sa, ((const float*)&vb)[c]);
                lb[c] = fmaf(0.5f, sb, ((const float*)&vb)[c]);
            }
            *(float4*)(ya + d * CC) = make_float4(la[0], la[1], la[2], la[3]);
            *(float4*)(yb + d * CC) = make_float4(lb[0], lb[1], lb[2], lb[3]);

            float ma = fmaxf(fmaxf(la[0], la[1]), fmaxf(la[2], la[3]));
            float sa = __expf(la[0] - ma) + __expf(la[1] - ma) +
                       __expf(la[2] - ma) + __expf(la[3] - ma);
            float lsa = ma + __logf(sa);
            *(float4*)(ya + pofs + d * CC) =
                make_float4(la[0] - lsa, la[1] - lsa, la[2] - lsa, la[3] - lsa);

            float mb = fmaxf(fmaxf(lb[0], lb[1]), fmaxf(lb[2], lb[3]));
            float sb = __expf(lb[0] - mb) + __expf(lb[1] - mb) +
                       __expf(lb[2] - mb) + __expf(lb[3] - mb);
            float lsb = mb + __logf(sb);
            *(float4*)(yb + pofs + d * CC) =
                make_float4(lb[0] - lsb, lb[1] - lsb, lb[2] - lsb, lb[3] - lsb);
        }
    }
}

extern "C" void kernel_launch(void* const* d_in, const int* in_sizes, int n_in,
                              void* d_out, int out_size) {
    const float* x    = (const float*)d_in[0];
    const float* V    = (const float*)d_in[1];
    const float* bias = (const float*)d_in[2];
    const float* W    = (const float*)d_in[3];
    const float* cvec = (const float*)d_in[4];
    float* out = (float*)d_out;

    nade_vb<<<(DD * CC) / 128, 512>>>(V, bias);
    nade_xt<<<dim3(BB / 32, DD / 32), dim3(32, 8)>>>(x);
    nade_phase1<<<dim3(HH / 16, BB / 32), 128>>>(W, cvec);
    nade_phase2<<<dim3(KK, BB / 64), 128>>>(V, W, out);
}

// round 7
// speedup vs baseline: 1.2880x; 1.2880x over previous
#include <cuda_runtime.h>

#define BB 512
#define DD 1024
#define HH 512
#define CC 4
#define DCH 8
#define KK (DD / DCH)       // 128 chunks
#define NSEG 4
#define HITER (HH / NSEG)   // 128 per hseg

// P'[k][h][b] = 0.5*(c + sum_{j<8k} x[b,j]W[h,j]); +BB pad for prefetch overrun
__device__ float g_P[((size_t)KK * HH + 1) * BB];      // ~134 MB, streamed
// xT[d][b] = 0.5 * x[b][d]
__device__ float g_XT[(size_t)DD * BB];
// vb[d][c] = bias[d][c] + 0.5 * sum_h V[h][d][c]
__device__ float g_VB[DD * CC];

__device__ __forceinline__ float tanh_fast(float a) {
    float th;
    asm("tanh.approx.f32 %0, %1;" : "=f"(th) : "f"(a));
    return th;
}

// ---------------- Phase 0a: vb = bias + 0.5 * sum_h V ----------------
// 32 blocks x 512 thr: 128 i's per block, h split 4 ways, smem reduce.
__global__ __launch_bounds__(512) void nade_vb(
    const float* __restrict__ V, const float* __restrict__ bias)
{
    __shared__ float part[4][128];
    const int il = threadIdx.x & 127;
    const int seg = threadIdx.x >> 7;            // 0..3
    const int i = blockIdx.x * 128 + il;
    float s = 0.f;
    const float* Vp = V + (size_t)(seg * 128) * (DD * CC) + i;
#pragma unroll 8
    for (int h = 0; h < 128; h++)
        s += __ldg(Vp + (size_t)h * (DD * CC));
    part[seg][il] = s;
    __syncthreads();
    if (seg == 0) {
        float t = part[0][il] + part[1][il] + part[2][il] + part[3][il];
        g_VB[i] = fmaf(0.5f, t, __ldg(&bias[i]));
    }
}

// ---------------- Phase 0b: xT[d][b] = 0.5 * x[b][d] ----------------
__global__ __launch_bounds__(256) void nade_xt(const float* __restrict__ x)
{
    __shared__ float tile[32][33];
    const int b0 = blockIdx.x * 32;
    const int d0 = blockIdx.y * 32;
    const int tx = threadIdx.x;       // 0..31
    const int ty = threadIdx.y;       // 0..7
#pragma unroll
    for (int r = 0; r < 4; r++)
        tile[ty + 8 * r][tx] = __ldg(&x[(size_t)(b0 + ty + 8 * r) * DD + d0 + tx]);
    __syncthreads();
#pragma unroll
    for (int r = 0; r < 4; r++)
        g_XT[(size_t)(d0 + ty + 8 * r) * BB + b0 + tx] = 0.5f * tile[tx][ty + 8 * r];
}

// ---------------- Phase 1: prefix GEMM, snapshots every 8 j ----------------
// grid (HH/16, BB/32), block 128: bl = tid&31 (b), hg = tid>>5 -> 4 h each.
__global__ __launch_bounds__(128) void nade_phase1(
    const float* __restrict__ W, const float* __restrict__ cvec)
{
    const int tid = threadIdx.x;
    const int bl = tid & 31;
    const int hg = tid >> 5;                       // 0..3
    const int hbase = blockIdx.x * 16 + hg * 4;    // 4 consecutive h
    const int b = blockIdx.y * 32 + bl;

    float acc[4];
#pragma unroll
    for (int m = 0; m < 4; m++) acc[m] = 0.5f * __ldg(&cvec[hbase + m]);

#pragma unroll 2
    for (int k = 0; k < KK; k++) {
        float* Pk = g_P + ((size_t)k * HH + hbase) * BB + b;
#pragma unroll
        for (int m = 0; m < 4; m++) Pk[(size_t)m * BB] = acc[m];

        float xv[DCH];
#pragma unroll
        for (int j = 0; j < DCH; j++)
            xv[j] = g_XT[(size_t)(k * DCH + j) * BB + b];          // coalesced L2

#pragma unroll
        for (int m = 0; m < 4; m++) {
            const float4* wr = (const float4*)(W + (size_t)(hbase + m) * DD + k * DCH);
#pragma unroll
            for (int q = 0; q < 2; q++) {
                float4 w = __ldg(&wr[q]);                           // warp-uniform
                acc[m] = fmaf(xv[4 * q + 0], w.x, acc[m]);
                acc[m] = fmaf(xv[4 * q + 1], w.y, acc[m]);
                acc[m] = fmaf(xv[4 * q + 2], w.z, acc[m]);
                acc[m] = fmaf(xv[4 * q + 3], w.w, acc[m]);
            }
        }
    }
}

// ---------------- Phase 2: per-chunk sequential NADE, 2 b per lane ----------------
// grid (KK, BB/64), block 128 = 4 warps (one per hseg). Lane: b0+lane, b0+lane+32.
__global__ __launch_bounds__(128, 4) void nade_phase2(
    const float* __restrict__ V, const float* __restrict__ W,
    float* __restrict__ out)
{
    __shared__ float ws[HH][DCH];                 // 16 KB: W[h][d0:d0+8]
    __shared__ float red[NSEG - 1][DCH * CC][64]; // 24 KB

    const int k = blockIdx.x;
    const int b0 = blockIdx.y * 64;
    const int tid = threadIdx.x;
    const int lane = tid & 31;
    const int hseg = tid >> 5;                    // 0..3
    const int ba = b0 + lane;
    const int bb = ba + 32;
    const int d0 = k * DCH;

    // stage W slice: 512 rows x 32B
    for (int i = tid; i < HH * 2; i += 128) {
        const int hh = i >> 1, q = i & 1;
        float4 wv = __ldg((const float4*)(W + (size_t)hh * DD + d0) + q);
        *(float4*)&ws[hh][q * 4] = wv;
    }

    // preload 0.5*x for both b (coalesced from xT)
    float xa[DCH], xb[DCH];
#pragma unroll
    for (int j = 0; j < DCH; j++) {
        const float* xr = &g_XT[(size_t)(d0 + j) * BB + b0];
        xa[j] = xr[lane];
        xb[j] = xr[lane + 32];
    }

    float acca[DCH][CC], accb[DCH][CC];
#pragma unroll
    for (int d = 0; d < DCH; d++)
#pragma unroll
        for (int c = 0; c < CC; c++) { acca[d][c] = 0.f; accb[d][c] = 0.f; }

    __syncthreads();

    const int hstart = hseg * HITER;
    const float* Pp = g_P + ((size_t)k * HH + hstart) * BB + ba;
    const float4* Vp = (const float4*)V + ((size_t)hstart * DD + d0);

    float a0n = __ldg(Pp);
    float a1n = __ldg(Pp + 32);
    for (int it = 0; it < HITER; ++it) {
        float a0 = a0n, a1 = a1n;
        Pp += BB;
        a0n = __ldg(Pp);                         // pad row protects last read
        a1n = __ldg(Pp + 32);
        const float* wr = ws[hstart + it];
#pragma unroll
        for (int q = 0; q < 2; q++) {
            float4 w4 = *(const float4*)(wr + 4 * q);   // broadcast LDS.128
            float wq[4] = {w4.x, w4.y, w4.z, w4.w};
#pragma unroll
            for (int r = 0; r < 4; r++) {
                const int d = 4 * q + r;
                float4 v = __ldg(Vp + d);               // warp-uniform, shared by both b
                float t0 = tanh_fast(a0);
                float t1 = tanh_fast(a1);
                acca[d][0] = fmaf(t0, v.x, acca[d][0]);
                acca[d][1] = fmaf(t0, v.y, acca[d][1]);
                acca[d][2] = fmaf(t0, v.z, acca[d][2]);
                acca[d][3] = fmaf(t0, v.w, acca[d][3]);
                accb[d][0] = fmaf(t1, v.x, accb[d][0]);
                accb[d][1] = fmaf(t1, v.y, accb[d][1]);
                accb[d][2] = fmaf(t1, v.z, accb[d][2]);
                accb[d][3] = fmaf(t1, v.w, accb[d][3]);
                a0 = fmaf(xa[d], wq[r], a0);            // halved-prefix advance
                a1 = fmaf(xb[d], wq[r], a1);
            }
        }
        Vp += DD;
    }

    if (hseg > 0) {
#pragma unroll
        for (int d = 0; d < DCH; d++)
#pragma unroll
            for (int c = 0; c < CC; c++) {
                red[hseg - 1][d * CC + c][lane] = acca[d][c];
                red[hseg - 1][d * CC + c][lane + 32] = accb[d][c];
            }
    }
    __syncthreads();

    if (hseg == 0) {
        float* ya = out + (size_t)ba * (DD * CC) + (size_t)d0 * CC;
        float* yb = out + (size_t)bb * (DD * CC) + (size_t)d0 * CC;
        const size_t pofs = (size_t)BB * DD * CC;
#pragma unroll
        for (int d = 0; d < DCH; d++) {
            const float4 vb = *(const float4*)&g_VB[(d0 + d) * CC];
            float la[4], lb[4];
#pragma unroll
            for (int c = 0; c < CC; c++) {
                float sa = acca[d][c] + red[0][d * CC + c][lane]
                         + red[1][d * CC + c][lane] + red[2][d * CC + c][lane];
                float sb = accb[d][c] + red[0][d * CC + c][lane + 32]
                         + red[1][d * CC + c][lane + 32] + red[2][d * CC + c][lane + 32];
                la[c] = fmaf(0.5f, sa, ((const float*)&vb)[c]);
                lb[c] = fmaf(0.5f, sb, ((const float*)&vb)[c]);
            }
            *(float4*)(ya + d * CC) = make_float4(la[0], la[1], la[2], la[3]);
            *(float4*)(yb + d * CC) = make_float4(lb[0], lb[1], lb[2], lb[3]);

            float ma = fmaxf(fmaxf(la[0], la[1]), fmaxf(la[2], la[3]));
            float sa = __expf(la[0] - ma) + __expf(la[1] - ma) +
                       __expf(la[2] - ma) + __expf(la[3] - ma);
            float lsa = ma + __logf(sa);
            *(float4*)(ya + pofs + d * CC) =
                make_float4(la[0] - lsa, la[1] - lsa, la[2] - lsa, la[3] - lsa);

            float mb = fmaxf(fmaxf(lb[0], lb[1]), fmaxf(lb[2], lb[3]));
            float sb = __expf(lb[0] - mb) + __expf(lb[1] - mb) +
                       __expf(lb[2] - mb) + __expf(lb[3] - mb);
            float lsb = mb + __logf(sb);
            *(float4*)(yb + pofs + d * CC) =
                make_float4(lb[0] - lsb, lb[1] - lsb, lb[2] - lsb, lb[3] - lsb);
        }
    }
}

extern "C" void kernel_launch(void* const* d_in, const int* in_sizes, int n_in,
                              void* d_out, int out_size) {
    const float* x    = (const float*)d_in[0];
    const float* V    = (const float*)d_in[1];
    const float* bias = (const float*)d_in[2];
    const float* W    = (const float*)d_in[3];
    const float* cvec = (const float*)d_in[4];
    float* out = (float*)d_out;

    nade_vb<<<(DD * CC) / 128, 512>>>(V, bias);
    nade_xt<<<dim3(BB / 32, DD / 32), dim3(32, 8)>>>(x);
    nade_phase1<<<dim3(HH / 16, BB / 32), 128>>>(W, cvec);
    nade_phase2<<<dim3(KK, BB / 64), 128>>>(V, W, out);
}

// round 8
// speedup vs baseline: 1.4145x; 1.0982x over previous
#include <cuda_runtime.h>

#define BB 512
#define DD 1024
#define HH 512
#define CC 4
#define DCH 8
#define KK (DD / DCH)       // 128 chunks
#define NSEG 4
#define HITER (HH / NSEG)   // 128 per hseg
#define PSEG 8              // phase1 k-segments
#define KSEG (KK / PSEG)    // 16 chunks per segment
#define JSEG (DD / PSEG)    // 128 j per segment

// P'[k][h][b] = 0.5*(c + sum_{j<8k} x[b,j]W[h,j]); +BB pad for prefetch overrun
__device__ float g_P[((size_t)KK * HH + 1) * BB];      // ~134 MB, streamed
// xT[d][b] = 0.5 * x[b][d]
__device__ float g_XT[(size_t)DD * BB];
// vb[d][c] = bias[d][c] + 0.5 * sum_h V[h][d][c]
__device__ float g_VB[DD * CC];
// S[s][h][b] = 0.5 * sum_{j in seg s} x[b,j] W[h,j]
__device__ float g_S[(size_t)PSEG * HH * BB];          // 4 MB, L2-resident

__device__ __forceinline__ float tanh_fast(float a) {
    float th;
    asm("tanh.approx.f32 %0, %1;" : "=f"(th) : "f"(a));
    return th;
}

// ---------------- Phase 0a: vb = bias + 0.5 * sum_h V ----------------
__global__ __launch_bounds__(512) void nade_vb(
    const float* __restrict__ V, const float* __restrict__ bias)
{
    __shared__ float part[4][128];
    const int il = threadIdx.x & 127;
    const int seg = threadIdx.x >> 7;            // 0..3
    const int i = blockIdx.x * 128 + il;
    float s = 0.f;
    const float* Vp = V + (size_t)(seg * 128) * (DD * CC) + i;
#pragma unroll 8
    for (int h = 0; h < 128; h++)
        s += __ldg(Vp + (size_t)h * (DD * CC));
    part[seg][il] = s;
    __syncthreads();
    if (seg == 0) {
        float t = part[0][il] + part[1][il] + part[2][il] + part[3][il];
        g_VB[i] = fmaf(0.5f, t, __ldg(&bias[i]));
    }
}

// ---------------- Phase 0b: xT[d][b] = 0.5 * x[b][d] ----------------
__global__ __launch_bounds__(256) void nade_xt(const float* __restrict__ x)
{
    __shared__ float tile[32][33];
    const int b0 = blockIdx.x * 32;
    const int d0 = blockIdx.y * 32;
    const int tx = threadIdx.x;       // 0..31
    const int ty = threadIdx.y;       // 0..7
#pragma unroll
    for (int r = 0; r < 4; r++)
        tile[ty + 8 * r][tx] = __ldg(&x[(size_t)(b0 + ty + 8 * r) * DD + d0 + tx]);
    __syncthreads();
#pragma unroll
    for (int r = 0; r < 4; r++)
        g_XT[(size_t)(d0 + ty + 8 * r) * BB + b0 + tx] = 0.5f * tile[tx][ty + 8 * r];
}

// ---------------- Phase 1a: segment sums S[s][h][b] ----------------
// grid (HH/16, BB/32, PSEG-1), block 128: bl=tid&31, hg=tid>>5 -> 4 h each.
__global__ __launch_bounds__(128) void nade_segsum(const float* __restrict__ W)
{
    const int tid = threadIdx.x;
    const int bl = tid & 31;
    const int hg = tid >> 5;
    const int hbase = blockIdx.x * 16 + hg * 4;
    const int b = blockIdx.y * 32 + bl;
    const int seg = blockIdx.z;            // 0..PSEG-2 (last seg's sum unused)
    const int j0 = seg * JSEG;

    float acc[4] = {0.f, 0.f, 0.f, 0.f};

#pragma unroll 2
    for (int k = 0; k < KSEG; k++) {
        float xv[DCH];
#pragma unroll
        for (int j = 0; j < DCH; j++)
            xv[j] = g_XT[(size_t)(j0 + k * DCH + j) * BB + b];

#pragma unroll
        for (int m = 0; m < 4; m++) {
            const float4* wr = (const float4*)(W + (size_t)(hbase + m) * DD + j0 + k * DCH);
#pragma unroll
            for (int q = 0; q < 2; q++) {
                float4 w = __ldg(&wr[q]);
                acc[m] = fmaf(xv[4 * q + 0], w.x, acc[m]);
                acc[m] = fmaf(xv[4 * q + 1], w.y, acc[m]);
                acc[m] = fmaf(xv[4 * q + 2], w.z, acc[m]);
                acc[m] = fmaf(xv[4 * q + 3], w.w, acc[m]);
            }
        }
    }
#pragma unroll
    for (int m = 0; m < 4; m++)
        g_S[((size_t)seg * HH + hbase + m) * BB + b] = acc[m];
}

// ---------------- Phase 1b: segmented snapshot writer ----------------
// grid (HH/16, BB/32, PSEG), block 128. Each thread: 4 h, one segment, 16 k-iters.
__global__ __launch_bounds__(128) void nade_phase1seg(
    const float* __restrict__ W, const float* __restrict__ cvec)
{
    const int tid = threadIdx.x;
    const int bl = tid & 31;
    const int hg = tid >> 5;
    const int hbase = blockIdx.x * 16 + hg * 4;
    const int b = blockIdx.y * 32 + bl;
    const int seg = blockIdx.z;            // 0..PSEG-1
    const int k0 = seg * KSEG;

    float acc[4];
#pragma unroll
    for (int m = 0; m < 4; m++) acc[m] = 0.5f * __ldg(&cvec[hbase + m]);
    for (int t = 0; t < seg; t++) {        // warp-uniform trip count
#pragma unroll
        for (int m = 0; m < 4; m++)
            acc[m] += g_S[((size_t)t * HH + hbase + m) * BB + b];
    }

#pragma unroll 2
    for (int k = k0; k < k0 + KSEG; k++) {
        float* Pk = g_P + ((size_t)k * HH + hbase) * BB + b;
#pragma unroll
        for (int m = 0; m < 4; m++) Pk[(size_t)m * BB] = acc[m];

        float xv[DCH];
#pragma unroll
        for (int j = 0; j < DCH; j++)
            xv[j] = g_XT[(size_t)(k * DCH + j) * BB + b];

#pragma unroll
        for (int m = 0; m < 4; m++) {
            const float4* wr = (const float4*)(W + (size_t)(hbase + m) * DD + k * DCH);
#pragma unroll
            for (int q = 0; q < 2; q++) {
                float4 w = __ldg(&wr[q]);
                acc[m] = fmaf(xv[4 * q + 0], w.x, acc[m]);
                acc[m] = fmaf(xv[4 * q + 1], w.y, acc[m]);
                acc[m] = fmaf(xv[4 * q + 2], w.z, acc[m]);
                acc[m] = fmaf(xv[4 * q + 3], w.w, acc[m]);
            }
        }
    }
}

// ---------------- Phase 2: per-chunk sequential NADE, 2 b per lane ----------------
// grid (KK, BB/64), block 128 = 4 warps (one per hseg). Lane: b0+lane, b0+lane+32.
__global__ __launch_bounds__(128, 4) void nade_phase2(
    const float* __restrict__ V, const float* __restrict__ W,
    float* __restrict__ out)
{
    __shared__ float ws[HH][DCH];                 // 16 KB: W[h][d0:d0+8]
    __shared__ float red[NSEG - 1][DCH * CC][64]; // 24 KB

    const int k = blockIdx.x;
    const int b0 = blockIdx.y * 64;
    const int tid = threadIdx.x;
    const int lane = tid & 31;
    const int hseg = tid >> 5;                    // 0..3
    const int ba = b0 + lane;
    const int bb = ba + 32;
    const int d0 = k * DCH;

    for (int i = tid; i < HH * 2; i += 128) {
        const int hh = i >> 1, q = i & 1;
        float4 wv = __ldg((const float4*)(W + (size_t)hh * DD + d0) + q);
        *(float4*)&ws[hh][q * 4] = wv;
    }

    float xa[DCH], xb[DCH];
#pragma unroll
    for (int j = 0; j < DCH; j++) {
        const float* xr = &g_XT[(size_t)(d0 + j) * BB + b0];
        xa[j] = xr[lane];
        xb[j] = xr[lane + 32];
    }

    float acca[DCH][CC], accb[DCH][CC];
#pragma unroll
    for (int d = 0; d < DCH; d++)
#pragma unroll
        for (int c = 0; c < CC; c++) { acca[d][c] = 0.f; accb[d][c] = 0.f; }

    __syncthreads();

    const int hstart = hseg * HITER;
    const float* Pp = g_P + ((size_t)k * HH + hstart) * BB + ba;
    const float4* Vp = (const float4*)V + ((size_t)hstart * DD + d0);

    float a0n = __ldg(Pp);
    float a1n = __ldg(Pp + 32);
    for (int it = 0; it < HITER; ++it) {
        float a0 = a0n, a1 = a1n;
        Pp += BB;
        a0n = __ldg(Pp);
        a1n = __ldg(Pp + 32);
        const float* wr = ws[hstart + it];
#pragma unroll
        for (int q = 0; q < 2; q++) {
            float4 w4 = *(const float4*)(wr + 4 * q);
            float wq[4] = {w4.x, w4.y, w4.z, w4.w};
#pragma unroll
            for (int r = 0; r < 4; r++) {
                const int d = 4 * q + r;
                float4 v = __ldg(Vp + d);
                float t0 = tanh_fast(a0);
                float t1 = tanh_fast(a1);
                acca[d][0] = fmaf(t0, v.x, acca[d][0]);
                acca[d][1] = fmaf(t0, v.y, acca[d][1]);
                acca[d][2] = fmaf(t0, v.z, acca[d][2]);
                acca[d][3] = fmaf(t0, v.w, acca[d][3]);
                accb[d][0] = fmaf(t1, v.x, accb[d][0]);
                accb[d][1] = fmaf(t1, v.y, accb[d][1]);
                accb[d][2] = fmaf(t1, v.z, accb[d][2]);
                accb[d][3] = fmaf(t1, v.w, accb[d][3]);
                a0 = fmaf(xa[d], wq[r], a0);
                a1 = fmaf(xb[d], wq[r], a1);
            }
        }
        Vp += DD;
    }

    if (hseg > 0) {
#pragma unroll
        for (int d = 0; d < DCH; d++)
#pragma unroll
            for (int c = 0; c < CC; c++) {
                red[hseg - 1][d * CC + c][lane] = acca[d][c];
                red[hseg - 1][d * CC + c][lane + 32] = accb[d][c];
            }
    }
    __syncthreads();

    if (hseg == 0) {
        float* ya = out + (size_t)ba * (DD * CC) + (size_t)d0 * CC;
        float* yb = out + (size_t)bb * (DD * CC) + (size_t)d0 * CC;
        const size_t pofs = (size_t)BB * DD * CC;
#pragma unroll
        for (int d = 0; d < DCH; d++) {
            const float4 vb = *(const float4*)&g_VB[(d0 + d) * CC];
            float la[4], lb[4];
#pragma unroll
            for (int c = 0; c < CC; c++) {
                float sa = acca[d][c] + red[0][d * CC + c][lane]
                         + red[1][d * CC + c][lane] + red[2][d * CC + c][lane];
                float sb = accb[d][c] + red[0][d * CC + c][lane + 32]
                         + red[1][d * CC + c][lane + 32] + red[2][d * CC + c][lane + 32];
                la[c] = fmaf(0.5f, sa, ((const float*)&vb)[c]);
                lb[c] = fmaf(0.5f, sb, ((const float*)&vb)[c]);
            }
            *(float4*)(ya + d * CC) = make_float4(la[0], la[1], la[2], la[3]);
            *(float4*)(yb + d * CC) = make_float4(lb[0], lb[1], lb[2], lb[3]);

            float ma = fmaxf(fmaxf(la[0], la[1]), fmaxf(la[2], la[3]));
            float sa = __expf(la[0] - ma) + __expf(la[1] - ma) +
                       __expf(la[2] - ma) + __expf(la[3] - ma);
            float lsa = ma + __logf(sa);
            *(float4*)(ya + pofs + d * CC) =
                make_float4(la[0] - lsa, la[1] - lsa, la[2] - lsa, la[3] - lsa);

            float mb = fmaxf(fmaxf(lb[0], lb[1]), fmaxf(lb[2], lb[3]));
            float sb = __expf(lb[0] - mb) + __expf(lb[1] - mb) +
                       __expf(lb[2] - mb) + __expf(lb[3] - mb);
            float lsb = mb + __logf(sb);
            *(float4*)(yb + pofs + d * CC) =
                make_float4(lb[0] - lsb, lb[1] - lsb, lb[2] - lsb, lb[3] - lsb);
        }
    }
}

extern "C" void kernel_launch(void* const* d_in, const int* in_sizes, int n_in,
                              void* d_out, int out_size) {
    const float* x    = (const float*)d_in[0];
    const float* V    = (const float*)d_in[1];
    const float* bias = (const float*)d_in[2];
    const float* W    = (const float*)d_in[3];
    const float* cvec = (const float*)d_in[4];
    float* out = (float*)d_out;

    nade_vb<<<(DD * CC) / 128, 512>>>(V, bias);
    nade_xt<<<dim3(BB / 32, DD / 32), dim3(32, 8)>>>(x);
    nade_segsum<<<dim3(HH / 16, BB / 32, PSEG - 1), 128>>>(W);
    nade_phase1seg<<<dim3(HH / 16, BB / 32, PSEG), 128>>>(W, cvec);
    nade_phase2<<<dim3(KK, BB / 64), 128>>>(V, W, out);
}

// round 9
// speedup vs baseline: 1.8754x; 1.3259x over previous
#include <cuda_runtime.h>

#define BB 512
#define DD 1024
#define HH 512
#define CC 4
#define DCH 8
#define KK (DD / DCH)       // 128 chunks
#define NSEG 4
#define HITER (HH / NSEG)   // 128 per hseg
#define PSEG 8              // phase1 k-segments
#define KSEG (KK / PSEG)    // 16 chunks per segment
#define JSEG (DD / PSEG)    // 128 j per segment

// P'[k][h][b] = 0.5*(c + sum_{j<8k} x[b,j]W[h,j]); +BB pad for prefetch overrun
__device__ float g_P[((size_t)KK * HH + 1) * BB];      // ~134 MB, streamed
// xT[d][b] = 0.5 * x[b][d]
__device__ float g_XT[(size_t)DD * BB];
// vb[d][c] = bias[d][c] + 0.5 * sum_h V[h][d][c]
__device__ float g_VB[DD * CC];
// S[s][h][b] = 0.5 * sum_{j in seg s} x[b,j] W[h,j]
__device__ float g_S[(size_t)PSEG * HH * BB];          // 4 MB, L2-resident

__device__ __forceinline__ float tanh_fast(float a) {
    float th;
    asm("tanh.approx.f32 %0, %1;" : "=f"(th) : "f"(a));
    return th;
}

// ---------------- Phase 0a: vb = bias + 0.5 * sum_h V ----------------
__global__ __launch_bounds__(512) void nade_vb(
    const float* __restrict__ V, const float* __restrict__ bias)
{
    __shared__ float part[4][128];
    const int il = threadIdx.x & 127;
    const int seg = threadIdx.x >> 7;            // 0..3
    const int i = blockIdx.x * 128 + il;
    float s = 0.f;
    const float* Vp = V + (size_t)(seg * 128) * (DD * CC) + i;
#pragma unroll 8
    for (int h = 0; h < 128; h++)
        s += __ldg(Vp + (size_t)h * (DD * CC));
    part[seg][il] = s;
    __syncthreads();
    if (seg == 0) {
        float t = part[0][il] + part[1][il] + part[2][il] + part[3][il];
        g_VB[i] = fmaf(0.5f, t, __ldg(&bias[i]));
    }
}

// ---------------- Phase 0b: xT[d][b] = 0.5 * x[b][d] ----------------
__global__ __launch_bounds__(256) void nade_xt(const float* __restrict__ x)
{
    __shared__ float tile[32][33];
    const int b0 = blockIdx.x * 32;
    const int d0 = blockIdx.y * 32;
    const int tx = threadIdx.x;       // 0..31
    const int ty = threadIdx.y;       // 0..7
#pragma unroll
    for (int r = 0; r < 4; r++)
        tile[ty + 8 * r][tx] = __ldg(&x[(size_t)(b0 + ty + 8 * r) * DD + d0 + tx]);
    __syncthreads();
#pragma unroll
    for (int r = 0; r < 4; r++)
        g_XT[(size_t)(d0 + ty + 8 * r) * BB + b0 + tx] = 0.5f * tile[tx][ty + 8 * r];
}

// ---------------- Phase 1a: segment sums S[s][h][b] ----------------
// grid (HH/16, BB/32, PSEG-1), block 128. W tile staged in smem, XT pipelined.
__global__ __launch_bounds__(128) void nade_segsum(const float* __restrict__ W)
{
    __shared__ float ws[16][JSEG];                 // 8 KB
    const int tid = threadIdx.x;
    const int bl = tid & 31;
    const int hg = tid >> 5;
    const int h0 = blockIdx.x * 16;
    const int hbase = h0 + hg * 4;
    const int b = blockIdx.y * 32 + bl;
    const int seg = blockIdx.z;
    const int j0 = seg * JSEG;

    for (int i = tid; i < 16 * 32; i += 128) {
        const int r = i >> 5, q = i & 31;
        *(float4*)&ws[r][q * 4] = __ldg((const float4*)(W + (size_t)(h0 + r) * DD + j0) + q);
    }

    float acc[4] = {0.f, 0.f, 0.f, 0.f};
    float xv[DCH];
#pragma unroll
    for (int j = 0; j < DCH; j++)
        xv[j] = g_XT[(size_t)(j0 + j) * BB + b];
    __syncthreads();

    for (int k = 0; k < KSEG; k++) {
        float xn[DCH];
        if (k + 1 < KSEG) {
#pragma unroll
            for (int j = 0; j < DCH; j++)
                xn[j] = g_XT[(size_t)(j0 + (k + 1) * DCH + j) * BB + b];
        }
#pragma unroll
        for (int m = 0; m < 4; m++) {
            const float* wr = &ws[hg * 4 + m][k * DCH];
#pragma unroll
            for (int q = 0; q < 2; q++) {
                float4 w = *(const float4*)(wr + 4 * q);   // broadcast LDS.128
                acc[m] = fmaf(xv[4 * q + 0], w.x, acc[m]);
                acc[m] = fmaf(xv[4 * q + 1], w.y, acc[m]);
                acc[m] = fmaf(xv[4 * q + 2], w.z, acc[m]);
                acc[m] = fmaf(xv[4 * q + 3], w.w, acc[m]);
            }
        }
#pragma unroll
        for (int j = 0; j < DCH; j++) xv[j] = xn[j];
    }
#pragma unroll
    for (int m = 0; m < 4; m++)
        g_S[((size_t)seg * HH + hbase + m) * BB + b] = acc[m];
}

// ---------------- Phase 1b: segmented snapshot writer ----------------
// grid (HH/16, BB/32, PSEG), block 128. smem W + XT pipeline + streaming P stores.
__global__ __launch_bounds__(128) void nade_phase1seg(
    const float* __restrict__ W, const float* __restrict__ cvec)
{
    __shared__ float ws[16][JSEG];                 // 8 KB
    const int tid = threadIdx.x;
    const int bl = tid & 31;
    const int hg = tid >> 5;
    const int h0 = blockIdx.x * 16;
    const int hbase = h0 + hg * 4;
    const int b = blockIdx.y * 32 + bl;
    const int seg = blockIdx.z;            // 0..PSEG-1
    const int j0 = seg * JSEG;
    const int k0 = seg * KSEG;

    for (int i = tid; i < 16 * 32; i += 128) {
        const int r = i >> 5, q = i & 31;
        *(float4*)&ws[r][q * 4] = __ldg((const float4*)(W + (size_t)(h0 + r) * DD + j0) + q);
    }

    float acc[4];
#pragma unroll
    for (int m = 0; m < 4; m++) acc[m] = 0.5f * __ldg(&cvec[hbase + m]);
    for (int t = 0; t < seg; t++) {        // warp-uniform trip count
#pragma unroll
        for (int m = 0; m < 4; m++)
            acc[m] += g_S[((size_t)t * HH + hbase + m) * BB + b];
    }

    float xv[DCH];
#pragma unroll
    for (int j = 0; j < DCH; j++)
        xv[j] = g_XT[(size_t)(j0 + j) * BB + b];
    __syncthreads();

    for (int kk = 0; kk < KSEG; kk++) {
        const int k = k0 + kk;
        float xn[DCH];
        if (kk + 1 < KSEG) {
#pragma unroll
            for (int j = 0; j < DCH; j++)
                xn[j] = g_XT[(size_t)(j0 + (kk + 1) * DCH + j) * BB + b];
        }

        float* Pk = g_P + ((size_t)k * HH + hbase) * BB + b;
#pragma unroll
        for (int m = 0; m < 4; m++)
            __stcs(Pk + (size_t)m * BB, acc[m]);       // streaming: read-once data

#pragma unroll
        for (int m = 0; m < 4; m++) {
            const float* wr = &ws[hg * 4 + m][kk * DCH];
#pragma unroll
            for (int q = 0; q < 2; q++) {
                float4 w = *(const float4*)(wr + 4 * q);   // broadcast LDS.128
                acc[m] = fmaf(xv[4 * q + 0], w.x, acc[m]);
                acc[m] = fmaf(xv[4 * q + 1], w.y, acc[m]);
                acc[m] = fmaf(xv[4 * q + 2], w.z, acc[m]);
                acc[m] = fmaf(xv[4 * q + 3], w.w, acc[m]);
            }
        }
#pragma unroll
        for (int j = 0; j < DCH; j++) xv[j] = xn[j];
    }
}

// ---------------- Phase 2: per-chunk sequential NADE, 2 b per lane ----------------
// grid (KK, BB/64), block 128 = 4 warps (one per hseg). Lane: b0+lane, b0+lane+32.
__global__ __launch_bounds__(128, 4) void nade_phase2(
    const float* __restrict__ V, const float* __restrict__ W,
    float* __restrict__ out)
{
    __shared__ float ws[HH][DCH];                 // 16 KB: W[h][d0:d0+8]
    __shared__ float red[NSEG - 1][DCH * CC][64]; // 24 KB

    const int k = blockIdx.x;
    const int b0 = blockIdx.y * 64;
    const int tid = threadIdx.x;
    const int lane = tid & 31;
    const int hseg = tid >> 5;                    // 0..3
    const int ba = b0 + lane;
    const int bb = ba + 32;
    const int d0 = k * DCH;

    for (int i = tid; i < HH * 2; i += 128) {
        const int hh = i >> 1, q = i & 1;
        float4 wv = __ldg((const float4*)(W + (size_t)hh * DD + d0) + q);
        *(float4*)&ws[hh][q * 4] = wv;
    }

    float xa[DCH], xb[DCH];
#pragma unroll
    for (int j = 0; j < DCH; j++) {
        const float* xr = &g_XT[(size_t)(d0 + j) * BB + b0];
        xa[j] = xr[lane];
        xb[j] = xr[lane + 32];
    }

    float acca[DCH][CC], accb[DCH][CC];
#pragma unroll
    for (int d = 0; d < DCH; d++)
#pragma unroll
        for (int c = 0; c < CC; c++) { acca[d][c] = 0.f; accb[d][c] = 0.f; }

    __syncthreads();

    const int hstart = hseg * HITER;
    const float* Pp = g_P + ((size_t)k * HH + hstart) * BB + ba;
    const float4* Vp = (const float4*)V + ((size_t)hstart * DD + d0);

    float a0n = __ldcs(Pp);
    float a1n = __ldcs(Pp + 32);
    for (int it = 0; it < HITER; ++it) {
        float a0 = a0n, a1 = a1n;
        Pp += BB;
        a0n = __ldcs(Pp);                        // pad row protects last read
        a1n = __ldcs(Pp + 32);
        const float* wr = ws[hstart + it];
#pragma unroll
        for (int q = 0; q < 2; q++) {
            float4 w4 = *(const float4*)(wr + 4 * q);
            float wq[4] = {w4.x, w4.y, w4.z, w4.w};
#pragma unroll
            for (int r = 0; r < 4; r++) {
                const int d = 4 * q + r;
                float4 v = __ldg(Vp + d);
                float t0 = tanh_fast(a0);
                float t1 = tanh_fast(a1);
                acca[d][0] = fmaf(t0, v.x, acca[d][0]);
                acca[d][1] = fmaf(t0, v.y, acca[d][1]);
                acca[d][2] = fmaf(t0, v.z, acca[d][2]);
                acca[d][3] = fmaf(t0, v.w, acca[d][3]);
                accb[d][0] = fmaf(t1, v.x, accb[d][0]);
                accb[d][1] = fmaf(t1, v.y, accb[d][1]);
                accb[d][2] = fmaf(t1, v.z, accb[d][2]);
                accb[d][3] = fmaf(t1, v.w, accb[d][3]);
                a0 = fmaf(xa[d], wq[r], a0);
                a1 = fmaf(xb[d], wq[r], a1);
            }
        }
        Vp += DD;
    }

    if (hseg > 0) {
#pragma unroll
        for (int d = 0; d < DCH; d++)
#pragma unroll
            for (int c = 0; c < CC; c++) {
                red[hseg - 1][d * CC + c][lane] = acca[d][c];
                red[hseg - 1][d * CC + c][lane + 32] = accb[d][c];
            }
    }
    __syncthreads();

    if (hseg == 0) {
        float* ya = out + (size_t)ba * (DD * CC) + (size_t)d0 * CC;
        float* yb = out + (size_t)bb * (DD * CC) + (size_t)d0 * CC;
        const size_t pofs = (size_t)BB * DD * CC;
#pragma unroll
        for (int d = 0; d < DCH; d++) {
            const float4 vb = *(const float4*)&g_VB[(d0 + d) * CC];
            float la[4], lb[4];
#pragma unroll
            for (int c = 0; c < CC; c++) {
                float sa = acca[d][c] + red[0][d * CC + c][lane]
                         + red[1][d * CC + c][lane] + red[2][d * CC + c][lane];
                float sb = accb[d][c] + red[0][d * CC + c][lane + 32]
                         + red[1][d * CC + c][lane + 32] + red[2][d * CC + c][lane + 32];
                la[c] = fmaf(0.5f, sa, ((const float*)&vb)[c]);
                lb[c] = fmaf(0.5f, sb, ((const float*)&vb)[c]);
            }
            *(float4*)(ya + d * CC) = make_float4(la[0], la[1], la[2], la[3]);
            *(float4*)(yb + d * CC) = make_float4(lb[0], lb[1], lb[2], lb[3]);

            float ma = fmaxf(fmaxf(la[0], la[1]), fmaxf(la[2], la[3]));
            float sa = __expf(la[0] - ma) + __expf(la[1] - ma) +
                       __expf(la[2] - ma) + __expf(la[3] - ma);
            float lsa = ma + __logf(sa);
            *(float4*)(ya + pofs + d * CC) =
                make_float4(la[0] - lsa, la[1] - lsa, la[2] - lsa, la[3] - lsa);

            float mb = fmaxf(fmaxf(lb[0], lb[1]), fmaxf(lb[2], lb[3]));
            float sb = __expf(lb[0] - mb) + __expf(lb[1] - mb) +
                       __expf(lb[2] - mb) + __expf(lb[3] - mb);
            float lsb = mb + __logf(sb);
            *(float4*)(yb + pofs + d * CC) =
                make_float4(lb[0] - lsb, lb[1] - lsb, lb[2] - lsb, lb[3] - lsb);
        }
    }
}

extern "C" void kernel_launch(void* const* d_in, const int* in_sizes, int n_in,
                              void* d_out, int out_size) {
    const float* x    = (const float*)d_in[0];
    const float* V    = (const float*)d_in[1];
    const float* bias = (const float*)d_in[2];
    const float* W    = (const float*)d_in[3];
    const float* cvec = (const float*)d_in[4];
    float* out = (float*)d_out;

    nade_vb<<<(DD * CC) / 128, 512>>>(V, bias);
    nade_xt<<<dim3(BB / 32, DD / 32), dim3(32, 8)>>>(x);
    nade_segsum<<<dim3(HH / 16, BB / 32, PSEG - 1), 128>>>(W);
    nade_phase1seg<<<dim3(HH / 16, BB / 32, PSEG), 128>>>(W, cvec);
    nade_phase2<<<dim3(KK, BB / 64), 128>>>(V, W, out);
}